// round 14
// baseline (speedup 1.0000x reference)
#include <cuda_runtime.h>
#include <cuda_fp16.h>
#include <cstdint>

// ---------------- problem dims ----------------
#define E_  100
#define B_  1024
#define D_  2048
#define H1_ 512
#define H2_ 256

// ---------------- scratch (__device__ globals; no cudaMalloc allowed) ----
__device__ __half g_xh [(size_t)B_ * D_];          //   4MB
__device__ __half g_w1h[(size_t)E_ * D_ * H1_];    // 210MB
__device__ __half g_w2h[(size_t)E_ * H1_ * H2_];   //  26MB
__device__ __half g_h1h[(size_t)E_ * B_ * H1_];    // 105MB

// ---------------- device helpers ----------------
__device__ __forceinline__ uint32_t smem_u32(const void* p) {
    uint32_t a;
    asm("{ .reg .u64 t; cvta.to.shared.u64 t, %1; cvt.u32.u64 %0, t; }" : "=r"(a) : "l"(p));
    return a;
}
__device__ __forceinline__ void cp_async16(uint32_t s, const void* g) {
    asm volatile("cp.async.cg.shared.global [%0], [%1], 16;" :: "r"(s), "l"(g));
}
__device__ __forceinline__ void cp_commit() {
    asm volatile("cp.async.commit_group;" ::: "memory");
}
__device__ __forceinline__ void ldsm4(uint32_t r[4], uint32_t addr) {
    asm volatile("ldmatrix.sync.aligned.m8n8.x4.shared.b16 {%0,%1,%2,%3}, [%4];"
        : "=r"(r[0]), "=r"(r[1]), "=r"(r[2]), "=r"(r[3]) : "r"(addr));
}
__device__ __forceinline__ void ldsm4t(uint32_t& r0, uint32_t& r1, uint32_t& r2, uint32_t& r3,
                                       uint32_t addr) {
    asm volatile("ldmatrix.sync.aligned.m8n8.x4.trans.shared.b16 {%0,%1,%2,%3}, [%4];"
        : "=r"(r0), "=r"(r1), "=r"(r2), "=r"(r3) : "r"(addr));
}
__device__ __forceinline__ void mma_f16(float c[4], const uint32_t a[4], const uint32_t b[2]) {
    asm volatile(
        "mma.sync.aligned.m16n8k16.row.col.f32.f16.f16.f32 "
        "{%0,%1,%2,%3}, {%4,%5,%6,%7}, {%8,%9}, {%0,%1,%2,%3};"
        : "+f"(c[0]), "+f"(c[1]), "+f"(c[2]), "+f"(c[3])
        : "r"(a[0]), "r"(a[1]), "r"(a[2]), "r"(a[3]), "r"(b[0]), "r"(b[1]));
}

// ---------------- shared geometry ----------------
#define MT 128
#define KC 64
#define A_STRIDE 144                 // 64 fp16 = 128B data + 16B pad
#define A_TILE_B (MT * A_STRIDE)     // 18432

// ================= LAYER 1 (R9/R13-proven, init-fold removed) =============
// 128x128 CTA, 4 warps (2m x 2n), warp tile 64x64, 2 CTAs/SM.
#define L1_NT 128
#define L1_B_STRIDE 272              // 128 fp16 = 256B + 16B pad
#define L1_B_TILE (KC * L1_B_STRIDE) // 17408
#define L1_STAGE (A_TILE_B + L1_B_TILE)  // 35840
#define L1_SMEM (1024 + 3 * L1_STAGE)    // 108544

__global__ void __launch_bounds__(128, 2)
gemm_l1(const __half* __restrict__ A, const __half* __restrict__ Bw,
        const float* __restrict__ bias, __half* __restrict__ C) {
    extern __shared__ __align__(128) char smem[];
    float* bias_s = reinterpret_cast<float*>(smem);
    const uint32_t sbase = smem_u32(smem) + 1024;
    const int tid = threadIdx.x, lane = tid & 31, warp = tid >> 5;
    const int wm = warp >> 1, wn = warp & 1;
    const int e = blockIdx.z, mt = blockIdx.y, nt = blockIdx.x;
    const int n0 = nt * L1_NT;

    bias_s[tid] = bias[(size_t)e * H1_ + n0 + tid];

    const char* Ab = (const char*)(A + (size_t)mt * MT * D_);      // shared x
    const char* Bb = (const char*)(Bw + (size_t)e * D_ * H1_ + n0);
    const int ldaB = D_ * 2;
    const int ldbB = H1_ * 2;

    auto load_stage = [&](int s, int c) {
        const uint32_t st = sbase + s * L1_STAGE;
        const char* Ac = Ab + c * KC * 2;
        #pragma unroll
        for (int it = 0; it < 8; it++) {
            int q = tid + it * 128;
            int r = q >> 3, seg = (q & 7) * 16;
            cp_async16(st + r * A_STRIDE + seg, Ac + (size_t)r * ldaB + seg);
        }
        const char* Bc = Bb + (size_t)(c * KC) * ldbB;
        const uint32_t stb = st + A_TILE_B;
        #pragma unroll
        for (int it = 0; it < 8; it++) {
            int q = tid + it * 128;
            int r = q >> 4, seg = (q & 15) * 16;
            cp_async16(stb + r * L1_B_STRIDE + seg, Bc + (size_t)r * ldbB + seg);
        }
    };

    const uint32_t offA = (uint32_t)(lane & 15) * A_STRIDE + (uint32_t)(lane >> 4) * 16;
    const uint32_t offB = (uint32_t)(lane & 15) * L1_B_STRIDE + (uint32_t)(lane >> 4) * 16;
    const uint32_t awoff = (uint32_t)wm * 64 * A_STRIDE + offA;
    const uint32_t bwoff = (uint32_t)wn * 128 + offB;

    uint32_t afr[2][4][4], bfr[2][8][2];
    auto prefetch = [&](uint32_t st, int ks, int buf) {
        const uint32_t sa = st + awoff + (uint32_t)ks * 32;
        #pragma unroll
        for (int i = 0; i < 4; i++)
            ldsm4(afr[buf][i], sa + (uint32_t)i * (16 * A_STRIDE));
        const uint32_t sb = st + A_TILE_B + bwoff + (uint32_t)ks * (16 * L1_B_STRIDE);
        #pragma unroll
        for (int j2 = 0; j2 < 4; j2++) {
            uint32_t r0, r1, r2, r3;
            ldsm4t(r0, r1, r2, r3, sb + (uint32_t)j2 * 32);
            bfr[buf][j2 * 2][0] = r0;     bfr[buf][j2 * 2][1] = r1;
            bfr[buf][j2 * 2 + 1][0] = r2; bfr[buf][j2 * 2 + 1][1] = r3;
        }
    };

    float acc[4][8][4];
    #pragma unroll
    for (int i = 0; i < 4; i++)
        #pragma unroll
        for (int j = 0; j < 8; j++)
            #pragma unroll
            for (int r = 0; r < 4; r++) acc[i][j][r] = 0.0f;

    load_stage(0, 0); cp_commit();
    load_stage(1, 1); cp_commit();
    asm volatile("cp.async.wait_group 1;" ::: "memory");
    __syncthreads();
    prefetch(sbase, 0, 0);

    const int nch = D_ / KC;
    for (int c = 0; c < nch; c++) {
        const uint32_t st = sbase + (c % 3) * L1_STAGE;
        if (c + 2 < nch) { load_stage((c + 2) % 3, c + 2); cp_commit(); }

        #pragma unroll
        for (int ks = 0; ks < 4; ks++) {
            const int cur = ks & 1;
            if (ks < 3) prefetch(st, ks + 1, cur ^ 1);
            #pragma unroll
            for (int i = 0; i < 4; i++)
                #pragma unroll
                for (int j = 0; j < 8; j++)
                    mma_f16(acc[i][j], afr[cur][i], bfr[cur][j]);
        }

        if (c + 1 < nch) {
            if (c + 2 < nch) { asm volatile("cp.async.wait_group 1;" ::: "memory"); }
            else             { asm volatile("cp.async.wait_group 0;" ::: "memory"); }
            __syncthreads();
            prefetch(sbase + ((c + 1) % 3) * L1_STAGE, 0, 0);
        }
    }

    // epilogue: bias + relu, store fp16 h1
    const int col0 = wn * 64 + (lane & 3) * 2;
    const int mrow0 = mt * MT + wm * 64 + (lane >> 2);
    __half* Ce = C + (size_t)e * (B_ * H1_) + n0;
    #pragma unroll
    for (int i = 0; i < 4; i++) {
        const size_t r0 = (size_t)(mrow0 + i * 16);
        #pragma unroll
        for (int j = 0; j < 8; j++) {
            const int col = col0 + j * 8;
            const float bx = bias_s[col], by = bias_s[col + 1];
            float v0 = fmaxf(acc[i][j][0] + bx, 0.0f);
            float v1 = fmaxf(acc[i][j][1] + by, 0.0f);
            float v2 = fmaxf(acc[i][j][2] + bx, 0.0f);
            float v3 = fmaxf(acc[i][j][3] + by, 0.0f);
            *reinterpret_cast<__half2*>(Ce + r0 * H1_ + col)       = __floats2half2_rn(v0, v1);
            *reinterpret_cast<__half2*>(Ce + (r0 + 8) * H1_ + col) = __floats2half2_rn(v2, v3);
        }
    }
}

// ================= LAYER 2 + fused LAYER 3, NT=256 (full H2 per CTA) ======
// 128x256 CTA, 8 warps (2m x 4n), warp tile 64x64, 1 CTA/SM (regs-bound).
// A-tile loaded once per (e,mt) (halves h1 traffic); layer-3 dot completes
// in-CTA via smem atomics into a b3-initialized buffer -> direct store,
// no global atomics, no init kernel.
#define L2_NT 256
#define L2_B_STRIDE 528              // 256 fp16 = 512B + 16B pad
#define L2_B_TILE (KC * L2_B_STRIDE) // 33792
#define L2_STAGE (A_TILE_B + L2_B_TILE)  // 52224
#define L2_SMEM (4096 + 3 * L2_STAGE)    // 160768

__global__ void __launch_bounds__(256, 1)
gemm_l2(const __half* __restrict__ A, const __half* __restrict__ Bw,
        const float* __restrict__ bias,
        const float* __restrict__ w3, const float* __restrict__ b3,
        float* __restrict__ outF) {
    extern __shared__ __align__(128) char smem[];
    float* bias_s = reinterpret_cast<float*>(smem);            // 256 f32
    float* w3_s   = reinterpret_cast<float*>(smem + 1024);     // 256 f32
    float* out_s  = reinterpret_cast<float*>(smem + 2048);     // 128 f32
    const uint32_t sbase = smem_u32(smem) + 4096;
    const int tid = threadIdx.x, lane = tid & 31, warp = tid >> 5;
    const int wm = warp >> 2, wn = warp & 3;                   // 2m x 4n
    const int mt = blockIdx.x, e = blockIdx.y;

    bias_s[tid] = bias[(size_t)e * H2_ + tid];
    w3_s[tid]   = w3[(size_t)e * H2_ + tid];
    if (tid < 128) out_s[tid] = b3[e];

    const char* Ab = (const char*)(A + ((size_t)e * B_ + (size_t)mt * MT) * H1_);
    const char* Bb = (const char*)(Bw + (size_t)e * H1_ * H2_);
    const int ldaB = H1_ * 2;
    const int ldbB = H2_ * 2;

    auto load_stage = [&](int s, int c) {
        const uint32_t st = sbase + s * L2_STAGE;
        const char* Ac = Ab + c * KC * 2;
        #pragma unroll
        for (int it = 0; it < 4; it++) {
            int q = tid + it * 256;              // 1024 slots: 128 rows x 8 segs
            int r = q >> 3, seg = (q & 7) * 16;
            cp_async16(st + r * A_STRIDE + seg, Ac + (size_t)r * ldaB + seg);
        }
        const char* Bc = Bb + (size_t)(c * KC) * ldbB;
        const uint32_t stb = st + A_TILE_B;
        #pragma unroll
        for (int it = 0; it < 8; it++) {
            int q = tid + it * 256;              // 2048 slots: 64 rows x 32 segs
            int r = q >> 5, seg = (q & 31) * 16;
            cp_async16(stb + r * L2_B_STRIDE + seg, Bc + (size_t)r * ldbB + seg);
        }
    };

    const uint32_t offA = (uint32_t)(lane & 15) * A_STRIDE + (uint32_t)(lane >> 4) * 16;
    const uint32_t offB = (uint32_t)(lane & 15) * L2_B_STRIDE + (uint32_t)(lane >> 4) * 16;
    const uint32_t awoff = (uint32_t)wm * 64 * A_STRIDE + offA;
    const uint32_t bwoff = (uint32_t)wn * 128 + offB;          // wn*64 cols * 2B

    uint32_t afr[2][4][4], bfr[2][8][2];
    auto prefetch = [&](uint32_t st, int ks, int buf) {
        const uint32_t sa = st + awoff + (uint32_t)ks * 32;
        #pragma unroll
        for (int i = 0; i < 4; i++)
            ldsm4(afr[buf][i], sa + (uint32_t)i * (16 * A_STRIDE));
        const uint32_t sb = st + A_TILE_B + bwoff + (uint32_t)ks * (16 * L2_B_STRIDE);
        #pragma unroll
        for (int j2 = 0; j2 < 4; j2++) {
            uint32_t r0, r1, r2, r3;
            ldsm4t(r0, r1, r2, r3, sb + (uint32_t)j2 * 32);
            bfr[buf][j2 * 2][0] = r0;     bfr[buf][j2 * 2][1] = r1;
            bfr[buf][j2 * 2 + 1][0] = r2; bfr[buf][j2 * 2 + 1][1] = r3;
        }
    };

    float acc[4][8][4];
    #pragma unroll
    for (int i = 0; i < 4; i++)
        #pragma unroll
        for (int j = 0; j < 8; j++)
            #pragma unroll
            for (int r = 0; r < 4; r++) acc[i][j][r] = 0.0f;

    load_stage(0, 0); cp_commit();
    load_stage(1, 1); cp_commit();
    asm volatile("cp.async.wait_group 1;" ::: "memory");
    __syncthreads();
    prefetch(sbase, 0, 0);

    const int nch = H1_ / KC;   // 8
    for (int c = 0; c < nch; c++) {
        const uint32_t st = sbase + (c % 3) * L2_STAGE;
        if (c + 2 < nch) { load_stage((c + 2) % 3, c + 2); cp_commit(); }

        #pragma unroll
        for (int ks = 0; ks < 4; ks++) {
            const int cur = ks & 1;
            if (ks < 3) prefetch(st, ks + 1, cur ^ 1);
            #pragma unroll
            for (int i = 0; i < 4; i++)
                #pragma unroll
                for (int j = 0; j < 8; j++)
                    mma_f16(acc[i][j], afr[cur][i], bfr[cur][j]);
        }

        if (c + 1 < nch) {
            if (c + 2 < nch) { asm volatile("cp.async.wait_group 1;" ::: "memory"); }
            else             { asm volatile("cp.async.wait_group 0;" ::: "memory"); }
            __syncthreads();
            prefetch(sbase + ((c + 1) % 3) * L2_STAGE, 0, 0);
        }
    }

    // fused layer-3 epilogue: each warp's 64-col partial dot -> smem atomics
    const int col0 = wn * 64 + (lane & 3) * 2;
    #pragma unroll
    for (int i = 0; i < 4; i++) {
        #pragma unroll
        for (int rr = 0; rr < 2; rr++) {
            float p = 0.0f;
            #pragma unroll
            for (int j = 0; j < 8; j++) {
                const int col = col0 + j * 8;
                float v0 = fmaxf(acc[i][j][rr * 2 + 0] + bias_s[col], 0.0f);
                float v1 = fmaxf(acc[i][j][rr * 2 + 1] + bias_s[col + 1], 0.0f);
                p += v0 * w3_s[col] + v1 * w3_s[col + 1];
            }
            p += __shfl_xor_sync(0xFFFFFFFFu, p, 1);
            p += __shfl_xor_sync(0xFFFFFFFFu, p, 2);
            if ((lane & 3) == 0)
                atomicAdd(&out_s[wm * 64 + i * 16 + rr * 8 + (lane >> 2)], p);
        }
    }
    __syncthreads();
    if (tid < 128)
        outF[(size_t)(mt * MT + tid) * E_ + e] = out_s[tid];
}

// ---------------- pre-pass: f32 -> f16 (single / dual) ----------------
__global__ void f32_to_f16_kernel(const float4* __restrict__ in, uint2* __restrict__ out,
                                  long n4) {
    long i = blockIdx.x * (long)blockDim.x + threadIdx.x;
    if (i < n4) {
        float4 v = in[i];
        __half2 lo = __floats2half2_rn(v.x, v.y);
        __half2 hi = __floats2half2_rn(v.z, v.w);
        uint2 o;
        o.x = *reinterpret_cast<uint32_t*>(&lo);
        o.y = *reinterpret_cast<uint32_t*>(&hi);
        out[i] = o;
    }
}
__global__ void f32_to_f16_dual(const float4* __restrict__ in1, uint2* __restrict__ out1, long n1,
                                const float4* __restrict__ in2, uint2* __restrict__ out2, long n2) {
    long i = blockIdx.x * (long)blockDim.x + threadIdx.x;
    const float4* in; uint2* out; long k;
    if (i < n1) { in = in1; out = out1; k = i; }
    else if (i < n1 + n2) { in = in2; out = out2; k = i - n1; }
    else return;
    float4 v = in[k];
    __half2 lo = __floats2half2_rn(v.x, v.y);
    __half2 hi = __floats2half2_rn(v.z, v.w);
    uint2 o;
    o.x = *reinterpret_cast<uint32_t*>(&lo);
    o.y = *reinterpret_cast<uint32_t*>(&hi);
    out[k] = o;
}

// ---------------- host ----------------
extern "C" void kernel_launch(void* const* d_in, const int* in_sizes, int n_in,
                              void* d_out, int out_size) {
    const float* x  = (const float*)d_in[0];
    const float* W1 = (const float*)d_in[1];
    const float* b1 = (const float*)d_in[2];
    const float* W2 = (const float*)d_in[3];
    const float* b2 = (const float*)d_in[4];
    const float* W3 = (const float*)d_in[5];
    const float* b3 = (const float*)d_in[6];
    float* out = (float*)d_out;

    __half *xh, *w1h, *w2h, *h1h;
    cudaGetSymbolAddress((void**)&xh,  g_xh);
    cudaGetSymbolAddress((void**)&w1h, g_w1h);
    cudaGetSymbolAddress((void**)&w2h, g_w2h);
    cudaGetSymbolAddress((void**)&h1h, g_h1h);

    cudaFuncSetAttribute(gemm_l1, cudaFuncAttributeMaxDynamicSharedMemorySize, L1_SMEM);
    cudaFuncSetAttribute(gemm_l2, cudaFuncAttributeMaxDynamicSharedMemorySize, L2_SMEM);

    // pre-convert: W1 (solo) + x & W2 (merged)
    {
        long n4w1 = (long)E_ * D_ * H1_ / 4;
        long n4x  = (long)B_ * D_ / 4;
        long n4w2 = (long)E_ * H1_ * H2_ / 4;
        f32_to_f16_kernel<<<(unsigned)((n4w1 + 255) / 256), 256>>>(
            (const float4*)W1, (uint2*)w1h, n4w1);
        f32_to_f16_dual<<<(unsigned)((n4x + n4w2 + 255) / 256), 256>>>(
            (const float4*)x,  (uint2*)xh,  n4x,
            (const float4*)W2, (uint2*)w2h, n4w2);
    }

    // layer 1: per-expert [1024,2048] x [2048,512], relu -> h1 (fp16)
    {
        dim3 grid(H1_ / L1_NT, B_ / MT, E_);   // (4, 8, 100)
        gemm_l1<<<grid, 128, L1_SMEM>>>(xh, w1h, b1, h1h);
    }
    // layer 2 + fused layer 3: one CTA per (mt, e) covers all H2=256 cols;
    // out[b][e] written directly (no global atomics, no init kernel)
    {
        dim3 grid(B_ / MT, E_);                // (8, 100)
        gemm_l2<<<grid, 256, L2_SMEM>>>(h1h, w2h, b2, W3, b3, out);
    }
}